// round 5
// baseline (speedup 1.0000x reference)
#include <cuda_runtime.h>
#include <math.h>

// ---------------- static config ----------------
#define BATCH 8
#define AA    8     // action channels (PA, P=1)
#define DD    8     // dim_qk
#define GRID  32    // T = H = W
#define THW   (32*32*32)

// tile per block
#define TT 4
#define TH 4
#define TW 32
#define NTHR 512    // == TT*TH*TW, one voxel per thread

// x tile with halo 2
#define XT (TT+4)   // 8
#define XH (TH+4)   // 8
#define XW (TW+4)   // 36
#define XSZ (XT*XH*XW)   // 2304

// k/v halo region (tile + halo 1)
#define KT (TT+2)   // 6
#define KH (TH+2)   // 6
#define KW (TW+2)   // 34
#define KHALO (KT*KH*KW) // 1224

#define SMEM_FLOATS (XSZ + DD*KHALO + KHALO + AA*27)   // 13536
#define SMEM_BYTES  (SMEM_FLOATS * 4)                  // 54144

// weights in constant memory: warp-uniform access -> ULDC path
__constant__ float c_wqk[128 * 27];   // [2*A*D][27]; q = rows 0..63, k = rows 64..127
__constant__ float c_wv [AA * 27];    // raw (pre-softmax) v weights

__global__ __launch_bounds__(NTHR, 2)
void avi_kernel(const float* __restrict__ values,
                const float* __restrict__ rewards,
                float* __restrict__ out)
{
    extern __shared__ float smem[];
    float* x_sm  = smem;                    // XSZ
    float* k_sm  = x_sm + XSZ;              // DD * KHALO
    float* v_sm  = k_sm + DD * KHALO;       // KHALO
    float* wv_sm = v_sm + KHALO;            // AA * 27 (softmaxed)

    const int tid  = threadIdx.x;
    const int b    = blockIdx.y;
    const int tile = blockIdx.x;            // 0..63
    const int t0   = (tile >> 3) * TT;
    const int h0   = (tile & 7)  * TH;

    const float* __restrict__ vb = values  + b * THW;
    const float* __restrict__ rb = rewards + b * THW;

    // ---- stage x = values + rewards with halo 2 (zero padded) ----
    for (int i = tid; i < XSZ; i += NTHR) {
        int xw = i % XW;
        int r  = i / XW;
        int xh = r % XH;
        int xt = r / XH;
        int gt = t0 - 2 + xt, gh = h0 - 2 + xh, gw = -2 + xw;
        float val = 0.f;
        if ((unsigned)gt < 32u && (unsigned)gh < 32u && (unsigned)gw < 32u) {
            int gi = (gt * 32 + gh) * 32 + gw;
            val = vb[gi] + rb[gi];
        }
        x_sm[i] = val;
    }

    // ---- softmax of w_v per action channel (27 taps) ----
    if (tid < AA) {
        float w[27];
        float m = -1e30f;
        #pragma unroll
        for (int j = 0; j < 27; j++) { w[j] = c_wv[tid * 27 + j]; m = fmaxf(m, w[j]); }
        float s = 0.f;
        #pragma unroll
        for (int j = 0; j < 27; j++) { w[j] = __expf(w[j] - m); s += w[j]; }
        float inv = 1.f / s;
        #pragma unroll
        for (int j = 0; j < 27; j++) wv_sm[tid * 27 + j] = w[j] * inv;
    }
    __syncthreads();

    // my voxel within the tile
    const int lw = tid & 31;
    const int lh = (tid >> 5) & 3;
    const int lt = tid >> 7;

    float best = -3.4e38f;

    for (int a = 0; a < AA; a++) {
        // ---- k (8 channels) + v over tile+halo1, masked to 0 outside grid ----
        for (int j = tid; j < KHALO; j += NTHR) {
            int kw = j % KW;
            int r  = j / KW;
            int kh = r % KH;
            int kt = r / KH;

            // cache the 27 x taps in registers; reuse across 9 output channels
            float xr[27];
            #pragma unroll
            for (int dt = 0; dt < 3; dt++)
                #pragma unroll
                for (int dh = 0; dh < 3; dh++)
                    #pragma unroll
                    for (int dw = 0; dw < 3; dw++)
                        xr[(dt * 3 + dh) * 3 + dw] =
                            x_sm[((kt + dt) * XH + (kh + dh)) * XW + (kw + dw)];

            int gt = t0 - 1 + kt, gh = h0 - 1 + kh, gw = -1 + kw;
            float vmask = ((unsigned)gt < 32u && (unsigned)gh < 32u && (unsigned)gw < 32u)
                          ? 1.f : 0.f;

            #pragma unroll
            for (int d = 0; d < DD; d++) {
                const float* wk = &c_wqk[(64 + a * DD + d) * 27];
                float acc = 0.f;
                #pragma unroll
                for (int tap = 0; tap < 27; tap++) acc = fmaf(wk[tap], xr[tap], acc);
                k_sm[d * KHALO + j] = acc * vmask;
            }
            {
                const float* wv = &wv_sm[a * 27];
                float acc = 0.f;
                #pragma unroll
                for (int tap = 0; tap < 27; tap++) acc = fmaf(wv[tap], xr[tap], acc);
                v_sm[j] = acc * vmask;
            }
        }
        __syncthreads();

        // ---- q[d] at my voxel (x neighborhood cached in registers) ----
        float xnb[27];
        #pragma unroll
        for (int dt = 0; dt < 3; dt++)
            #pragma unroll
            for (int dh = 0; dh < 3; dh++)
                #pragma unroll
                for (int dw = 0; dw < 3; dw++)
                    xnb[(dt * 3 + dh) * 3 + dw] =
                        x_sm[((lt + 1 + dt) * XH + (lh + 1 + dh)) * XW + (lw + 1 + dw)];

        float q[DD];
        #pragma unroll
        for (int d = 0; d < DD; d++) {
            const float* wq = &c_wqk[(a * DD + d) * 27];
            float acc = 0.f;
            #pragma unroll
            for (int tap = 0; tap < 27; tap++) acc = fmaf(wq[tap], xnb[tap], acc);
            q[d] = acc;
        }

        // ---- online softmax over the 27 offsets, fused with v dot ----
        float m = -3.4e38f, num = 0.f, den = 0.f;
        #pragma unroll
        for (int dt = 0; dt < 3; dt++)
            #pragma unroll
            for (int dh = 0; dh < 3; dh++)
                #pragma unroll
                for (int dw = 0; dw < 3; dw++) {
                    int base = ((lt + dt) * KH + (lh + dh)) * KW + (lw + dw);
                    float s = 0.f;
                    #pragma unroll
                    for (int d = 0; d < DD; d++)
                        s = fmaf(q[d], k_sm[d * KHALO + base], s);
                    float nm = fmaxf(m, s);
                    float c0 = __expf(m - nm);   // 0 on first iteration
                    float c1 = __expf(s - nm);
                    num = num * c0 + c1 * v_sm[base];
                    den = den * c0 + c1;
                    m = nm;
                }

        best = fmaxf(best, num / den);
        __syncthreads();   // protect k_sm/v_sm before next action overwrites
    }

    out[b * THW + ((t0 + lt) * 32 + (h0 + lh)) * 32 + lw] = best;
}

extern "C" void kernel_launch(void* const* d_in, const int* in_sizes, int n_in,
                              void* d_out, int out_size)
{
    const float* values  = (const float*)d_in[0];
    const float* rewards = (const float*)d_in[1];
    const float* w_qk    = (const float*)d_in[2];
    const float* w_v     = (const float*)d_in[3];
    float* out = (float*)d_out;

    // stage weights into constant memory (D2D async copies: graph-capturable)
    cudaMemcpyToSymbolAsync(c_wqk, w_qk, 128 * 27 * sizeof(float), 0,
                            cudaMemcpyDeviceToDevice, 0);
    cudaMemcpyToSymbolAsync(c_wv,  w_v,  AA * 27 * sizeof(float), 0,
                            cudaMemcpyDeviceToDevice, 0);

    cudaFuncSetAttribute(avi_kernel, cudaFuncAttributeMaxDynamicSharedMemorySize,
                         SMEM_BYTES);

    dim3 grid(64, BATCH);   // 64 spatial tiles (8x8 of 4x4x32) x 8 batches
    avi_kernel<<<grid, NTHR, SMEM_BYTES>>>(values, rewards, out);
}

// round 8
// speedup vs baseline: 1.0006x; 1.0006x over previous
#include <cuda_runtime.h>
#include <math.h>

// ---------------- static config ----------------
#define BATCH 8
#define AA    8     // action channels (PA, P=1)
#define DD    8     // dim_qk
#define GRID  32    // T = H = W
#define THW   (32*32*32)

// tile per block
#define TT 4
#define TH 4
#define TW 32
#define NTHR 512    // == TT*TH*TW, one voxel per thread

// x tile with halo 2
#define XT (TT+4)   // 8
#define XH (TH+4)   // 8
#define XW (TW+4)   // 36
#define XSZ (XT*XH*XW)   // 2304

// k/v halo region (tile + halo 1)
#define KT (TT+2)   // 6
#define KH (TH+2)   // 6
#define KW (TW+2)   // 34
#define KHALO (KT*KH*KW) // 1224

#define SMEM_FLOATS (XSZ + DD*KHALO + KHALO + AA*27)   // 13536
#define SMEM_BYTES  (SMEM_FLOATS * 4)                  // 54144

// weights in constant memory: warp-uniform access -> ULDC path
__constant__ float c_wqk[128 * 27];   // [2*A*D][27]; q = rows 0..63, k = rows 64..127
__constant__ float c_wv [AA * 27];    // raw (pre-softmax) v weights

__global__ __launch_bounds__(NTHR, 2)
void avi_kernel(const float* __restrict__ values,
                const float* __restrict__ rewards,
                float* __restrict__ out)
{
    extern __shared__ float smem[];
    float* x_sm  = smem;                    // XSZ
    float* k_sm  = x_sm + XSZ;              // DD * KHALO
    float* v_sm  = k_sm + DD * KHALO;       // KHALO
    float* wv_sm = v_sm + KHALO;            // AA * 27 (softmaxed)

    const int tid  = threadIdx.x;
    const int b    = blockIdx.y;
    const int tile = blockIdx.x;            // 0..63
    const int t0   = (tile >> 3) * TT;
    const int h0   = (tile & 7)  * TH;

    const float* __restrict__ vb = values  + b * THW;
    const float* __restrict__ rb = rewards + b * THW;

    // ---- stage x = values + rewards with halo 2 (zero padded) ----
    for (int i = tid; i < XSZ; i += NTHR) {
        int xw = i % XW;
        int r  = i / XW;
        int xh = r % XH;
        int xt = r / XH;
        int gt = t0 - 2 + xt, gh = h0 - 2 + xh, gw = -2 + xw;
        float val = 0.f;
        if ((unsigned)gt < 32u && (unsigned)gh < 32u && (unsigned)gw < 32u) {
            int gi = (gt * 32 + gh) * 32 + gw;
            val = vb[gi] + rb[gi];
        }
        x_sm[i] = val;
    }

    // ---- softmax of w_v per action channel (27 taps) ----
    if (tid < AA) {
        float w[27];
        float m = -1e30f;
        #pragma unroll
        for (int j = 0; j < 27; j++) { w[j] = c_wv[tid * 27 + j]; m = fmaxf(m, w[j]); }
        float s = 0.f;
        #pragma unroll
        for (int j = 0; j < 27; j++) { w[j] = __expf(w[j] - m); s += w[j]; }
        float inv = 1.f / s;
        #pragma unroll
        for (int j = 0; j < 27; j++) wv_sm[tid * 27 + j] = w[j] * inv;
    }
    __syncthreads();

    // my voxel within the tile
    const int lw = tid & 31;
    const int lh = (tid >> 5) & 3;
    const int lt = tid >> 7;

    float best = -3.4e38f;

    for (int a = 0; a < AA; a++) {
        // ---- k (8 channels) + v over tile+halo1, masked to 0 outside grid ----
        for (int j = tid; j < KHALO; j += NTHR) {
            int kw = j % KW;
            int r  = j / KW;
            int kh = r % KH;
            int kt = r / KH;

            // cache the 27 x taps in registers; reuse across 9 output channels
            float xr[27];
            #pragma unroll
            for (int dt = 0; dt < 3; dt++)
                #pragma unroll
                for (int dh = 0; dh < 3; dh++)
                    #pragma unroll
                    for (int dw = 0; dw < 3; dw++)
                        xr[(dt * 3 + dh) * 3 + dw] =
                            x_sm[((kt + dt) * XH + (kh + dh)) * XW + (kw + dw)];

            int gt = t0 - 1 + kt, gh = h0 - 1 + kh, gw = -1 + kw;
            float vmask = ((unsigned)gt < 32u && (unsigned)gh < 32u && (unsigned)gw < 32u)
                          ? 1.f : 0.f;

            #pragma unroll
            for (int d = 0; d < DD; d++) {
                const float* wk = &c_wqk[(64 + a * DD + d) * 27];
                float acc = 0.f;
                #pragma unroll
                for (int tap = 0; tap < 27; tap++) acc = fmaf(wk[tap], xr[tap], acc);
                k_sm[d * KHALO + j] = acc * vmask;
            }
            {
                const float* wv = &wv_sm[a * 27];
                float acc = 0.f;
                #pragma unroll
                for (int tap = 0; tap < 27; tap++) acc = fmaf(wv[tap], xr[tap], acc);
                v_sm[j] = acc * vmask;
            }
        }
        __syncthreads();

        // ---- q[d] at my voxel (x neighborhood cached in registers) ----
        float xnb[27];
        #pragma unroll
        for (int dt = 0; dt < 3; dt++)
            #pragma unroll
            for (int dh = 0; dh < 3; dh++)
                #pragma unroll
                for (int dw = 0; dw < 3; dw++)
                    xnb[(dt * 3 + dh) * 3 + dw] =
                        x_sm[((lt + 1 + dt) * XH + (lh + 1 + dh)) * XW + (lw + 1 + dw)];

        float q[DD];
        #pragma unroll
        for (int d = 0; d < DD; d++) {
            const float* wq = &c_wqk[(a * DD + d) * 27];
            float acc = 0.f;
            #pragma unroll
            for (int tap = 0; tap < 27; tap++) acc = fmaf(wq[tap], xnb[tap], acc);
            q[d] = acc;
        }

        // ---- online softmax over the 27 offsets, fused with v dot ----
        float m = -3.4e38f, num = 0.f, den = 0.f;
        #pragma unroll
        for (int dt = 0; dt < 3; dt++)
            #pragma unroll
            for (int dh = 0; dh < 3; dh++)
                #pragma unroll
                for (int dw = 0; dw < 3; dw++) {
                    int base = ((lt + dt) * KH + (lh + dh)) * KW + (lw + dw);
                    float s = 0.f;
                    #pragma unroll
                    for (int d = 0; d < DD; d++)
                        s = fmaf(q[d], k_sm[d * KHALO + base], s);
                    float nm = fmaxf(m, s);
                    float c0 = __expf(m - nm);   // 0 on first iteration
                    float c1 = __expf(s - nm);
                    num = num * c0 + c1 * v_sm[base];
                    den = den * c0 + c1;
                    m = nm;
                }

        best = fmaxf(best, num / den);
        __syncthreads();   // protect k_sm/v_sm before next action overwrites
    }

    out[b * THW + ((t0 + lt) * 32 + (h0 + lh)) * 32 + lw] = best;
}

extern "C" void kernel_launch(void* const* d_in, const int* in_sizes, int n_in,
                              void* d_out, int out_size)
{
    const float* values  = (const float*)d_in[0];
    const float* rewards = (const float*)d_in[1];
    const float* w_qk    = (const float*)d_in[2];
    const float* w_v     = (const float*)d_in[3];
    float* out = (float*)d_out;

    // stage weights into constant memory (D2D async copies: graph-capturable)
    cudaMemcpyToSymbolAsync(c_wqk, w_qk, 128 * 27 * sizeof(float), 0,
                            cudaMemcpyDeviceToDevice, 0);
    cudaMemcpyToSymbolAsync(c_wv,  w_v,  AA * 27 * sizeof(float), 0,
                            cudaMemcpyDeviceToDevice, 0);

    cudaFuncSetAttribute(avi_kernel, cudaFuncAttributeMaxDynamicSharedMemorySize,
                         SMEM_BYTES);

    dim3 grid(64, BATCH);   // 64 spatial tiles (8x8 of 4x4x32) x 8 batches
    avi_kernel<<<grid, NTHR, SMEM_BYTES>>>(values, rewards, out);
}